// round 9
// baseline (speedup 1.0000x reference)
#include <cuda_runtime.h>

#define NB 16
#define NA 3
#define NM 32
#define NC 80
#define NH 80
#define NW 80
#define NHW (NH * NW)                 // 6400
#define CH (NA * (5 + NC) + NA * NM)  // 351
#define NE (NB * NA * NHW)            // 307200
#define TPB 128
#define EPT 2
#define EPB (TPB * EPT)               // 256
#define NWARP (TPB / 32)              // 4
#define NBLK (NE / EPB)               // 1200
#define THRESH 0.05f
#define STRIDEF 8.0f
#define ROW (7 + NM)                  // 39

// state word: bits[63:62] flag (0=invalid, 1=AGG, 2=PRE), bit[61] round parity,
// bits[31:0] count. Stale entries from the previous launch carry the opposite
// parity and read as not-ready; no reset kernel needed.
__device__ unsigned long long g_state[NBLK];   // zero-init at module load
__device__ int g_round = 0;

__global__ void __launch_bounds__(TPB, 12)
fused_kernel(const float* __restrict__ in, const float* __restrict__ anchors,
             float* __restrict__ out, long long out_size)
{
    const int tid  = threadIdx.x;
    const int lane = tid & 31;
    const int wid  = tid >> 5;
    const int bid  = blockIdx.x;

    const unsigned round = (unsigned)*(volatile const int*)&g_round;

    const int e0 = bid * EPB + tid * EPT;
    const int b  = e0 / (NA * NHW);
    const int r  = e0 - b * (NA * NHW);
    const int a  = r / NHW;
    const int p  = r - a * NHW;          // even; both elems share (b,a) and grid row

    const float* base = in + ((size_t)b * CH + (size_t)a * (5 + NC)) * NHW + p;

    // ---- max-free softmax (2 lanes per thread, float2 loads) ----
    float m0 = -1e30f, m1 = -1e30f;
    float s0 = 0.f, s1 = 0.f;
    int i0 = 0, i1 = 0;
    const float2* cb = (const float2*)(base + 5 * NHW);
#pragma unroll 10
    for (int c = 0; c < NC; ++c) {
        float2 x = __ldg(cb + c * (NHW / 2));
        s0 += __expf(x.x); if (x.x > m0) { m0 = x.x; i0 = c; }
        s1 += __expf(x.y); if (x.y > m1) { m1 = x.y; i1 = c; }
    }

    const float2 oraw = __ldg((const float2*)(base + 4 * NHW));
    const float obj0 = 1.0f / (1.0f + expf(-oraw.x));   // accurate: threshold-critical
    const float obj1 = 1.0f / (1.0f + expf(-oraw.y));
    const float score0 = obj0 * __expf(m0) / s0;
    const float score1 = obj1 * __expf(m1) / s1;
    const bool keep0 = score0 > THRESH;
    const bool keep1 = score1 > THRESH;

    // ---- block rank via count scan (EPT=2) ----
    __shared__ int s_warp[NWARP];
    __shared__ int s_base;
    const int kc = (int)keep0 + (int)keep1;
    int incl = kc;
#pragma unroll
    for (int d = 1; d < 32; d <<= 1) {
        int n = __shfl_up_sync(0xffffffffu, incl, d);
        if (lane >= d) incl += n;
    }
    if (lane == 31) s_warp[wid] = incl;
    __syncthreads();
    if (wid == 0 && lane < NWARP) {
        int w = s_warp[lane];
#pragma unroll
        for (int d = 1; d < NWARP; d <<= 1) {
            int n = __shfl_up_sync(0xfu, w, d);
            if (lane >= d) w += n;
        }
        s_warp[lane] = w;
    }
    __syncthreads();
    const int total = s_warp[NWARP - 1];
    const int texcl = (wid ? s_warp[wid - 1] : 0) + incl - kc;

    const unsigned long long RB   = (unsigned long long)round << 61;
    const unsigned long long AGGT = (1ull << 62) | RB;
    const unsigned long long PRET = (2ull << 62) | RB;

    // ---- decoupled lookback (warp 0), round-tagged ----
    if (wid == 0) {
        if (bid == 0) {
            if (lane == 0) {
                atomicExch(&g_state[0], PRET | (unsigned)total);
                s_base = 0;
            }
        } else {
            if (lane == 0)
                atomicExch(&g_state[bid], AGGT | (unsigned)total);
            int excl = 0;
            int j = bid - 1;
            while (j >= 0) {
                const int gidx = j - lane;
                const bool valid = gidx >= 0;
                unsigned long long v;
                bool ready;
                bool first = true;
                do {
                    if (!first) __nanosleep(40);
                    first = false;
                    v = valid ? *(volatile const unsigned long long*)&g_state[gidx]
                              : PRET;
                    ready = ((v >> 62) != 0ull) &&
                            ((unsigned)((v >> 61) & 1ull) == round);
                } while (__any_sync(0xffffffffu, !ready));
                const unsigned pmask = __ballot_sync(0xffffffffu, (v >> 62) == 2ull);
                const int cut = pmask ? (__ffs(pmask) - 1) : 32;
                const unsigned add = (lane <= (cut < 31 ? cut : 31)) ? (unsigned)(v & 0xffffffffu) : 0u;
                excl += (int)__reduce_add_sync(0xffffffffu, add);
                if (cut < 32) break;
                j -= 32;
            }
            if (lane == 0) {
                atomicExch(&g_state[bid], PRET | (unsigned)(excl + total));
                s_base = excl;
            }
        }
        if (bid == NBLK - 1 && lane == 0)
            *(volatile int*)&g_round = (int)(round ^ 1u);
    }
    __syncthreads();

    if (total == 0) return;

    const int row0 = s_base + texcl;
    const int row1 = row0 + (int)keep0;
    const long long o0 = (long long)row0 * ROW;
    const long long o1 = (long long)row1 * ROW;
    const bool wok0 = keep0 && (o0 + ROW <= out_size);
    const bool wok1 = keep1 && (o1 + ROW <= out_size);

    if (wok0 | wok1) {
        const float2 x0 = __ldg((const float2*)(base + 0 * NHW));
        const float2 y0 = __ldg((const float2*)(base + 1 * NHW));
        const float2 w0 = __ldg((const float2*)(base + 2 * NHW));
        const float2 h0 = __ldg((const float2*)(base + 3 * NHW));

        const float aw = anchors[a * 2 + 0];
        const float ah = anchors[a * 2 + 1];
        const float amax = fmaxf(fmaxf(fmaxf(anchors[0], anchors[1]),
                                       fmaxf(anchors[2], anchors[3])),
                                 fmaxf(anchors[4], anchors[5]));
        const float maxv = floorf(logf(1e35f / amax / STRIDEF));
        const float linx = (float)(p % NW);
        const float liny = (float)(p / NW);

        if (wok0) {
            out[o0 + 0] = (float)b;
            out[o0 + 1] = (1.0f / (1.0f + __expf(-x0.x)) + linx) * STRIDEF;
            out[o0 + 2] = (1.0f / (1.0f + __expf(-y0.x)) + liny) * STRIDEF;
            out[o0 + 3] = __expf(fminf(w0.x, maxv)) * aw * STRIDEF;
            out[o0 + 4] = __expf(fminf(h0.x, maxv)) * ah * STRIDEF;
            out[o0 + 5 + NM] = score0;
            out[o0 + 6 + NM] = (float)i0;
        }
        if (wok1) {
            out[o1 + 0] = (float)b;
            out[o1 + 1] = (1.0f / (1.0f + __expf(-x0.y)) + linx + 1.0f) * STRIDEF;
            out[o1 + 2] = (1.0f / (1.0f + __expf(-y0.y)) + liny) * STRIDEF;
            out[o1 + 3] = __expf(fminf(w0.y, maxv)) * aw * STRIDEF;
            out[o1 + 4] = __expf(fminf(h0.y, maxv)) * ah * STRIDEF;
            out[o1 + 5 + NM] = score1;
            out[o1 + 6 + NM] = (float)i1;
        }

        const float2* mb = (const float2*)(in + ((size_t)b * CH + NA * (5 + NC) + (size_t)a * NM) * NHW + p);
#pragma unroll 8
        for (int mi = 0; mi < NM; ++mi) {
            float2 mv = __ldg(mb + mi * (NHW / 2));
            if (wok0) out[o0 + 5 + mi] = mv.x;
            if (wok1) out[o1 + 5 + mi] = mv.y;
        }
    }
}

extern "C" void kernel_launch(void* const* d_in, const int* in_sizes, int n_in,
                              void* d_out, int out_size)
{
    const float* in      = (const float*)d_in[0];
    const float* anchors = (const float*)d_in[1];
    float* out = (float*)d_out;

    fused_kernel<<<NBLK, TPB>>>(in, anchors, out, (long long)out_size);
}

// round 10
// speedup vs baseline: 1.2625x; 1.2625x over previous
#include <cuda_runtime.h>

#define NB 16
#define NA 3
#define NM 32
#define NC 80
#define NH 80
#define NW 80
#define NHW (NH * NW)                 // 6400
#define CH (NA * (5 + NC) + NA * NM)  // 351
#define NE (NB * NA * NHW)            // 307200
#define TPB 256
#define NWARP (TPB / 32)              // 8
#define NBLK (NE / TPB)               // 1200
#define THRESH 0.05f
#define STRIDEF 8.0f
#define ROW (7 + NM)                  // 39
#define STAGE 128                     // staged rows per block (mean keep ~69)

// state word: bits[63:62] flag (0=invalid, 1=AGG, 2=PRE), bit[61] round parity,
// bits[31:0] count. Stale entries from the previous launch carry the opposite
// parity and read as not-ready; no reset kernel needed.
__device__ unsigned long long g_state[NBLK];   // zero-init at module load
__device__ int g_round = 0;

__global__ void __launch_bounds__(TPB, 6)
fused_kernel(const float* __restrict__ in, const float* __restrict__ anchors,
             float* __restrict__ out, long long out_size)
{
    __shared__ float s_stage[STAGE * ROW];     // 19968 B
    __shared__ int   s_warp[NWARP];
    __shared__ int   s_base;

    const int tid  = threadIdx.x;
    const int lane = tid & 31;
    const int wid  = tid >> 5;
    const int bid  = blockIdx.x;

    const unsigned round = (unsigned)*(volatile const int*)&g_round;

    const int e = bid * TPB + tid;
    const int b = e / (NA * NHW);
    const int r = e - b * (NA * NHW);
    const int a = r / NHW;
    const int p = r - a * NHW;

    const float* base = in + ((size_t)b * CH + (size_t)a * (5 + NC)) * NHW + p;

    // ---- max-free softmax over NC logits: cls_max = exp(m)/sum(exp(x)) ----
    float m = -1e30f, s = 0.0f;
    int idx = 0;
    const float* cb = base + 5 * NHW;
#pragma unroll 10
    for (int c = 0; c < NC; ++c) {
        float x = __ldg(cb + c * NHW);
        s += __expf(x);
        if (x > m) { m = x; idx = c; }
    }

    const float obj = 1.0f / (1.0f + expf(-__ldg(base + 4 * NHW)));  // accurate
    const float score = obj * __expf(m) / s;
    const bool keep = score > THRESH;

    // ---- block rank ----
    const unsigned ball = __ballot_sync(0xffffffffu, keep);
    if (lane == 0) s_warp[wid] = __popc(ball);
    __syncthreads();
    int texcl = 0, total = 0;
#pragma unroll
    for (int i = 0; i < NWARP; ++i) {
        int c = s_warp[i];
        if (i < wid) texcl += c;
        total += c;
    }
    texcl += __popc(ball & ((1u << lane) - 1u));

    const unsigned long long RB   = (unsigned long long)round << 61;
    const unsigned long long AGGT = (1ull << 62) | RB;
    const unsigned long long PRET = (2ull << 62) | RB;

    // ---- stage this thread's row into smem (overlaps warp0 lookback) ----
    const float* mb = in + ((size_t)b * CH + NA * (5 + NC) + (size_t)a * NM) * NHW + p;

    // warp0 first publishes AGG + resolves the prefix; warps 1..7 stage now.
    if (wid == 0) {
        if (bid == 0) {
            if (lane == 0) {
                atomicExch(&g_state[0], PRET | (unsigned)total);
                s_base = 0;
            }
        } else {
            if (lane == 0)
                atomicExch(&g_state[bid], AGGT | (unsigned)total);
            int excl = 0;
            int j = bid - 1;
            while (j >= 0) {
                const int gidx = j - lane;
                const bool valid = gidx >= 0;
                unsigned long long v;
                bool ready;
                bool first = true;
                do {
                    if (!first) __nanosleep(40);
                    first = false;
                    v = valid ? *(volatile const unsigned long long*)&g_state[gidx]
                              : PRET;
                    ready = ((v >> 62) != 0ull) &&
                            ((unsigned)((v >> 61) & 1ull) == round);
                } while (__any_sync(0xffffffffu, !ready));
                const unsigned pmask = __ballot_sync(0xffffffffu, (v >> 62) == 2ull);
                const int cut = pmask ? (__ffs(pmask) - 1) : 32;
                const unsigned add = (lane <= (cut < 31 ? cut : 31)) ? (unsigned)(v & 0xffffffffu) : 0u;
                excl += (int)__reduce_add_sync(0xffffffffu, add);
                if (cut < 32) break;
                j -= 32;
            }
            if (lane == 0) {
                atomicExch(&g_state[bid], PRET | (unsigned)(excl + total));
                s_base = excl;
            }
        }
        if (bid == NBLK - 1 && lane == 0)
            *(volatile int*)&g_round = (int)(round ^ 1u);
    }

    if (keep && texcl < STAGE) {
        float* rowp = s_stage + texcl * ROW;

        const float x0 = __ldg(base + 0 * NHW);
        const float y0 = __ldg(base + 1 * NHW);
        const float w0 = __ldg(base + 2 * NHW);
        const float h0 = __ldg(base + 3 * NHW);

        const float aw = anchors[a * 2 + 0];
        const float ah = anchors[a * 2 + 1];
        const float amax = fmaxf(fmaxf(fmaxf(anchors[0], anchors[1]),
                                       fmaxf(anchors[2], anchors[3])),
                                 fmaxf(anchors[4], anchors[5]));
        const float maxv = floorf(logf(1e35f / amax / STRIDEF));

        rowp[0] = (float)b;
        rowp[1] = (1.0f / (1.0f + __expf(-x0)) + (float)(p % NW)) * STRIDEF;
        rowp[2] = (1.0f / (1.0f + __expf(-y0)) + (float)(p / NW)) * STRIDEF;
        rowp[3] = __expf(fminf(w0, maxv)) * aw * STRIDEF;
        rowp[4] = __expf(fminf(h0, maxv)) * ah * STRIDEF;
        rowp[5 + NM] = score;
        rowp[6 + NM] = (float)idx;
#pragma unroll 8
        for (int mi = 0; mi < NM; ++mi)
            rowp[5 + mi] = __ldg(mb + mi * NHW);
    }
    __syncthreads();

    if (total == 0) return;
    const long long obase = (long long)s_base * ROW;

    // ---- coalesced block copy of staged rows ----
    const int nfl = (total < STAGE ? total : STAGE) * ROW;
    for (int i = tid; i < nfl; i += TPB) {
        const long long oi = obase + i;
        if (oi < out_size) out[oi] = s_stage[i];
    }

    // ---- rare overflow (>STAGE kept rows): direct scattered write ----
    if (keep && texcl >= STAGE) {
        const long long o = obase + (long long)texcl * ROW;
        if (o + ROW <= out_size) {
            const float x0 = __ldg(base + 0 * NHW);
            const float y0 = __ldg(base + 1 * NHW);
            const float w0 = __ldg(base + 2 * NHW);
            const float h0 = __ldg(base + 3 * NHW);
            const float aw = anchors[a * 2 + 0];
            const float ah = anchors[a * 2 + 1];
            const float amax = fmaxf(fmaxf(fmaxf(anchors[0], anchors[1]),
                                           fmaxf(anchors[2], anchors[3])),
                                     fmaxf(anchors[4], anchors[5]));
            const float maxv = floorf(logf(1e35f / amax / STRIDEF));
            out[o + 0] = (float)b;
            out[o + 1] = (1.0f / (1.0f + __expf(-x0)) + (float)(p % NW)) * STRIDEF;
            out[o + 2] = (1.0f / (1.0f + __expf(-y0)) + (float)(p / NW)) * STRIDEF;
            out[o + 3] = __expf(fminf(w0, maxv)) * aw * STRIDEF;
            out[o + 4] = __expf(fminf(h0, maxv)) * ah * STRIDEF;
            out[o + 5 + NM] = score;
            out[o + 6 + NM] = (float)idx;
#pragma unroll 8
            for (int mi = 0; mi < NM; ++mi)
                out[o + 5 + mi] = __ldg(mb + mi * NHW);
        }
    }
}

extern "C" void kernel_launch(void* const* d_in, const int* in_sizes, int n_in,
                              void* d_out, int out_size)
{
    const float* in      = (const float*)d_in[0];
    const float* anchors = (const float*)d_in[1];
    float* out = (float*)d_out;

    fused_kernel<<<NBLK, TPB>>>(in, anchors, out, (long long)out_size);
}

// round 11
// speedup vs baseline: 1.3991x; 1.1082x over previous
#include <cuda_runtime.h>

#define NB 16
#define NA 3
#define NM 32
#define NC 80
#define NH 80
#define NW 80
#define NHW (NH * NW)                 // 6400
#define CH (NA * (5 + NC) + NA * NM)  // 351
#define NE (NB * NA * NHW)            // 307200
#define TPB 256
#define NWARP (TPB / 32)              // 8
#define NBLK (NE / TPB)               // 1200
#define THRESH 0.05f
#define STRIDEF 8.0f
#define ROW (7 + NM)                  // 39
#define STAGE 128                     // staged rows per block (mean keep ~69)

// state word: bits[63:62] flag (0=invalid, 1=AGG, 2=PRE), bit[61] round parity,
// bits[31:0] count. Stale entries from the previous launch carry the opposite
// parity and read as not-ready; no reset kernel needed.
__device__ unsigned long long g_state[NBLK];   // zero-init at module load
__device__ int g_round = 0;

__global__ void __launch_bounds__(TPB, 8)
fused_kernel(const float* __restrict__ in, const float* __restrict__ anchors,
             float* __restrict__ out, long long out_size)
{
    __shared__ float s_stage[STAGE * ROW];     // 19968 B
    __shared__ int   s_warp[NWARP];
    __shared__ int   s_base;

    const int tid  = threadIdx.x;
    const int lane = tid & 31;
    const int wid  = tid >> 5;
    const int bid  = blockIdx.x;

    const unsigned round = (unsigned)*(volatile const int*)&g_round;

    const int e = bid * TPB + tid;
    const int b = e / (NA * NHW);
    const int r = e - b * (NA * NHW);
    const int a = r / NHW;
    const int p = r - a * NHW;

    const float* base = in + ((size_t)b * CH + (size_t)a * (5 + NC)) * NHW + p;

    // ---- max-free softmax over NC logits: cls_max = exp(m)/sum(exp(x)) ----
    float m = -1e30f, s = 0.0f;
    int idx = 0;
    const float* cb = base + 5 * NHW;
#pragma unroll 10
    for (int c = 0; c < NC; ++c) {
        float x = __ldg(cb + c * NHW);
        s += __expf(x);
        if (x > m) { m = x; idx = c; }
    }

    const float obj = 1.0f / (1.0f + expf(-__ldg(base + 4 * NHW)));  // accurate
    const float score = obj * __expf(m) / s;
    const bool keep = score > THRESH;

    // ---- block rank ----
    const unsigned ball = __ballot_sync(0xffffffffu, keep);
    if (lane == 0) s_warp[wid] = __popc(ball);
    __syncthreads();
    int texcl = 0, total = 0;
#pragma unroll
    for (int i = 0; i < NWARP; ++i) {
        int c = s_warp[i];
        if (i < wid) texcl += c;
        total += c;
    }
    texcl += __popc(ball & ((1u << lane) - 1u));

    const unsigned long long RB   = (unsigned long long)round << 61;
    const unsigned long long AGGT = (1ull << 62) | RB;
    const unsigned long long PRET = (2ull << 62) | RB;

    // warp0 publishes AGG + resolves prefix; warps 1..7 stage rows meanwhile.
    if (wid == 0) {
        if (bid == 0) {
            if (lane == 0) {
                atomicExch(&g_state[0], PRET | (unsigned)total);
                s_base = 0;
            }
        } else {
            if (lane == 0)
                atomicExch(&g_state[bid], AGGT | (unsigned)total);
            int excl = 0;
            int j = bid - 1;
            while (j >= 0) {
                const int gidx = j - lane;
                const bool valid = gidx >= 0;
                unsigned long long v;
                bool ready;
                bool first = true;
                do {
                    if (!first) __nanosleep(40);
                    first = false;
                    v = valid ? *(volatile const unsigned long long*)&g_state[gidx]
                              : PRET;
                    ready = ((v >> 62) != 0ull) &&
                            ((unsigned)((v >> 61) & 1ull) == round);
                } while (__any_sync(0xffffffffu, !ready));
                const unsigned pmask = __ballot_sync(0xffffffffu, (v >> 62) == 2ull);
                const int cut = pmask ? (__ffs(pmask) - 1) : 32;
                const unsigned add = (lane <= (cut < 31 ? cut : 31)) ? (unsigned)(v & 0xffffffffu) : 0u;
                excl += (int)__reduce_add_sync(0xffffffffu, add);
                if (cut < 32) break;
                j -= 32;
            }
            if (lane == 0) {
                atomicExch(&g_state[bid], PRET | (unsigned)(excl + total));
                s_base = excl;
            }
        }
        if (bid == NBLK - 1 && lane == 0)
            *(volatile int*)&g_round = (int)(round ^ 1u);
    }

    // ---- stage this thread's row into smem (overlaps warp0 lookback) ----
    if (keep && texcl < STAGE) {
        float* rowp = s_stage + texcl * ROW;

        const float x0 = __ldg(base + 0 * NHW);
        const float y0 = __ldg(base + 1 * NHW);
        const float w0 = __ldg(base + 2 * NHW);
        const float h0 = __ldg(base + 3 * NHW);

        const float aw = anchors[a * 2 + 0];
        const float ah = anchors[a * 2 + 1];
        const float amax = fmaxf(fmaxf(fmaxf(anchors[0], anchors[1]),
                                       fmaxf(anchors[2], anchors[3])),
                                 fmaxf(anchors[4], anchors[5]));
        const float maxv = floorf(logf(1e35f / amax / STRIDEF));

        rowp[0] = (float)b;
        rowp[1] = (1.0f / (1.0f + __expf(-x0)) + (float)(p % NW)) * STRIDEF;
        rowp[2] = (1.0f / (1.0f + __expf(-y0)) + (float)(p / NW)) * STRIDEF;
        rowp[3] = __expf(fminf(w0, maxv)) * aw * STRIDEF;
        rowp[4] = __expf(fminf(h0, maxv)) * ah * STRIDEF;
        rowp[5 + NM] = score;
        rowp[6 + NM] = (float)idx;

        const float* mb = in + ((size_t)b * CH + NA * (5 + NC) + (size_t)a * NM) * NHW + p;
#pragma unroll 8
        for (int mi = 0; mi < NM; ++mi)
            rowp[5 + mi] = __ldg(mb + mi * NHW);
    }
    __syncthreads();

    if (total == 0) return;
    const long long obase = (long long)s_base * ROW;

    // ---- coalesced block copy of staged rows ----
    const int nfl = (total < STAGE ? total : STAGE) * ROW;
    if (obase + nfl <= out_size) {
        for (int i = tid; i < nfl; i += TPB)
            out[obase + i] = s_stage[i];
    } else {
        for (int i = tid; i < nfl; i += TPB) {
            const long long oi = obase + i;
            if (oi < out_size) out[oi] = s_stage[i];
        }
    }

    // ---- rare overflow (>STAGE kept rows): direct scattered write ----
    if (keep && texcl >= STAGE) {
        const long long o = obase + (long long)texcl * ROW;
        if (o + ROW <= out_size) {
            const float x0 = __ldg(base + 0 * NHW);
            const float y0 = __ldg(base + 1 * NHW);
            const float w0 = __ldg(base + 2 * NHW);
            const float h0 = __ldg(base + 3 * NHW);
            const float aw = anchors[a * 2 + 0];
            const float ah = anchors[a * 2 + 1];
            const float amax = fmaxf(fmaxf(fmaxf(anchors[0], anchors[1]),
                                           fmaxf(anchors[2], anchors[3])),
                                     fmaxf(anchors[4], anchors[5]));
            const float maxv = floorf(logf(1e35f / amax / STRIDEF));
            out[o + 0] = (float)b;
            out[o + 1] = (1.0f / (1.0f + __expf(-x0)) + (float)(p % NW)) * STRIDEF;
            out[o + 2] = (1.0f / (1.0f + __expf(-y0)) + (float)(p / NW)) * STRIDEF;
            out[o + 3] = __expf(fminf(w0, maxv)) * aw * STRIDEF;
            out[o + 4] = __expf(fminf(h0, maxv)) * ah * STRIDEF;
            out[o + 5 + NM] = score;
            out[o + 6 + NM] = (float)idx;
            const float* mb = in + ((size_t)b * CH + NA * (5 + NC) + (size_t)a * NM) * NHW + p;
#pragma unroll 8
            for (int mi = 0; mi < NM; ++mi)
                out[o + 5 + mi] = __ldg(mb + mi * NHW);
        }
    }
}

extern "C" void kernel_launch(void* const* d_in, const int* in_sizes, int n_in,
                              void* d_out, int out_size)
{
    const float* in      = (const float*)d_in[0];
    const float* anchors = (const float*)d_in[1];
    float* out = (float*)d_out;

    fused_kernel<<<NBLK, TPB>>>(in, anchors, out, (long long)out_size);
}

// round 12
// speedup vs baseline: 1.5347x; 1.0969x over previous
#include <cuda_runtime.h>

#define NB 16
#define NA 3
#define NM 32
#define NC 80
#define NH 80
#define NW 80
#define NHW (NH * NW)                 // 6400
#define CH (NA * (5 + NC) + NA * NM)  // 351
#define NE (NB * NA * NHW)            // 307200
#define TPB 256
#define NWARP (TPB / 32)              // 8
#define NBLK (NE / TPB)               // 1200
#define THRESH 0.05f
#define STRIDEF 8.0f
#define ROW (7 + NM)                  // 39
#define STAGE 128                     // staged rows per block (mean keep ~69)

// state word: bits[63:62] flag (0=invalid, 1=AGG, 2=PRE), bit[61] round parity,
// bits[31:0] count. Stale entries from the previous launch carry the opposite
// parity and read as not-ready; no reset kernel needed.
__device__ unsigned long long g_state[NBLK];   // zero-init at module load
__device__ int g_round = 0;

__global__ void __launch_bounds__(TPB, 7)
fused_kernel(const float* __restrict__ in, const float* __restrict__ anchors,
             float* __restrict__ out, long long out_size)
{
    __shared__ float s_stage[STAGE * ROW];     // 19968 B
    __shared__ int   s_warp[NWARP];
    __shared__ int   s_base;

    const int tid  = threadIdx.x;
    const int lane = tid & 31;
    const int wid  = tid >> 5;
    const int bid  = blockIdx.x;

    const unsigned round = (unsigned)*(volatile const int*)&g_round;

    const int e = bid * TPB + tid;
    const int b = e / (NA * NHW);
    const int r = e - b * (NA * NHW);
    const int a = r / NHW;
    const int p = r - a * NHW;

    const float* base = in + ((size_t)b * CH + (size_t)a * (5 + NC)) * NHW + p;

    // ---- max-free softmax, double-buffered 8-wide pipeline ----
    // batch t+1's loads are issued before batch t is consumed -> 8..16
    // outstanding LDGs per thread throughout the stream.
    const float* cb = base + 5 * NHW;
    float xa[8], xb[8];
#pragma unroll
    for (int i = 0; i < 8; ++i) xa[i] = __ldg(cb + i * NHW);

    float m = -1e30f, s = 0.0f;
    int idx = 0;
#pragma unroll
    for (int t = 0; t < NC / 8; ++t) {
        if (t + 1 < NC / 8) {
#pragma unroll
            for (int i = 0; i < 8; ++i) {
                float v = __ldg(cb + ((t + 1) * 8 + i) * NHW);
                if (t & 1) xa[i] = v; else xb[i] = v;
            }
        }
#pragma unroll
        for (int i = 0; i < 8; ++i) {
            float x = (t & 1) ? xb[i] : xa[i];
            s += __expf(x);
            if (x > m) { m = x; idx = t * 8 + i; }
        }
    }

    const float obj = 1.0f / (1.0f + expf(-__ldg(base + 4 * NHW)));  // accurate
    const float score = obj * __expf(m) / s;
    const bool keep = score > THRESH;

    // ---- block rank ----
    const unsigned ball = __ballot_sync(0xffffffffu, keep);
    if (lane == 0) s_warp[wid] = __popc(ball);
    __syncthreads();
    int texcl = 0, total = 0;
#pragma unroll
    for (int i = 0; i < NWARP; ++i) {
        int c = s_warp[i];
        if (i < wid) texcl += c;
        total += c;
    }
    texcl += __popc(ball & ((1u << lane) - 1u));

    const unsigned long long RB   = (unsigned long long)round << 61;
    const unsigned long long AGGT = (1ull << 62) | RB;
    const unsigned long long PRET = (2ull << 62) | RB;

    // warp0 publishes AGG + resolves prefix; warps 1..7 stage rows meanwhile.
    if (wid == 0) {
        if (bid == 0) {
            if (lane == 0) {
                atomicExch(&g_state[0], PRET | (unsigned)total);
                s_base = 0;
            }
        } else {
            if (lane == 0)
                atomicExch(&g_state[bid], AGGT | (unsigned)total);
            int excl = 0;
            int j = bid - 1;
            while (j >= 0) {
                const int gidx = j - lane;
                const bool valid = gidx >= 0;
                unsigned long long v;
                bool ready;
                bool first = true;
                do {
                    if (!first) __nanosleep(40);
                    first = false;
                    v = valid ? *(volatile const unsigned long long*)&g_state[gidx]
                              : PRET;
                    ready = ((v >> 62) != 0ull) &&
                            ((unsigned)((v >> 61) & 1ull) == round);
                } while (__any_sync(0xffffffffu, !ready));
                const unsigned pmask = __ballot_sync(0xffffffffu, (v >> 62) == 2ull);
                const int cut = pmask ? (__ffs(pmask) - 1) : 32;
                const unsigned add = (lane <= (cut < 31 ? cut : 31)) ? (unsigned)(v & 0xffffffffu) : 0u;
                excl += (int)__reduce_add_sync(0xffffffffu, add);
                if (cut < 32) break;
                j -= 32;
            }
            if (lane == 0) {
                atomicExch(&g_state[bid], PRET | (unsigned)(excl + total));
                s_base = excl;
            }
        }
        if (bid == NBLK - 1 && lane == 0)
            *(volatile int*)&g_round = (int)(round ^ 1u);
    }

    // ---- stage this thread's row into smem (overlaps warp0 lookback) ----
    if (keep && texcl < STAGE) {
        float* rowp = s_stage + texcl * ROW;

        const float x0 = __ldg(base + 0 * NHW);
        const float y0 = __ldg(base + 1 * NHW);
        const float w0 = __ldg(base + 2 * NHW);
        const float h0 = __ldg(base + 3 * NHW);

        const float aw = anchors[a * 2 + 0];
        const float ah = anchors[a * 2 + 1];
        const float amax = fmaxf(fmaxf(fmaxf(anchors[0], anchors[1]),
                                       fmaxf(anchors[2], anchors[3])),
                                 fmaxf(anchors[4], anchors[5]));
        const float maxv = floorf(logf(1e35f / amax / STRIDEF));

        rowp[0] = (float)b;
        rowp[1] = (1.0f / (1.0f + __expf(-x0)) + (float)(p % NW)) * STRIDEF;
        rowp[2] = (1.0f / (1.0f + __expf(-y0)) + (float)(p / NW)) * STRIDEF;
        rowp[3] = __expf(fminf(w0, maxv)) * aw * STRIDEF;
        rowp[4] = __expf(fminf(h0, maxv)) * ah * STRIDEF;
        rowp[5 + NM] = score;
        rowp[6 + NM] = (float)idx;

        const float* mb = in + ((size_t)b * CH + NA * (5 + NC) + (size_t)a * NM) * NHW + p;
#pragma unroll 8
        for (int mi = 0; mi < NM; ++mi)
            rowp[5 + mi] = __ldg(mb + mi * NHW);
    }
    __syncthreads();

    if (total == 0) return;
    const long long obase = (long long)s_base * ROW;

    // ---- coalesced block copy of staged rows ----
    const int nfl = (total < STAGE ? total : STAGE) * ROW;
    if (obase + nfl <= out_size) {
        for (int i = tid; i < nfl; i += TPB)
            out[obase + i] = s_stage[i];
    } else {
        for (int i = tid; i < nfl; i += TPB) {
            const long long oi = obase + i;
            if (oi < out_size) out[oi] = s_stage[i];
        }
    }

    // ---- rare overflow (>STAGE kept rows): direct scattered write ----
    if (keep && texcl >= STAGE) {
        const long long o = obase + (long long)texcl * ROW;
        if (o + ROW <= out_size) {
            const float x0 = __ldg(base + 0 * NHW);
            const float y0 = __ldg(base + 1 * NHW);
            const float w0 = __ldg(base + 2 * NHW);
            const float h0 = __ldg(base + 3 * NHW);
            const float aw = anchors[a * 2 + 0];
            const float ah = anchors[a * 2 + 1];
            const float amax = fmaxf(fmaxf(fmaxf(anchors[0], anchors[1]),
                                           fmaxf(anchors[2], anchors[3])),
                                     fmaxf(anchors[4], anchors[5]));
            const float maxv = floorf(logf(1e35f / amax / STRIDEF));
            out[o + 0] = (float)b;
            out[o + 1] = (1.0f / (1.0f + __expf(-x0)) + (float)(p % NW)) * STRIDEF;
            out[o + 2] = (1.0f / (1.0f + __expf(-y0)) + (float)(p / NW)) * STRIDEF;
            out[o + 3] = __expf(fminf(w0, maxv)) * aw * STRIDEF;
            out[o + 4] = __expf(fminf(h0, maxv)) * ah * STRIDEF;
            out[o + 5 + NM] = score;
            out[o + 6 + NM] = (float)idx;
            const float* mb = in + ((size_t)b * CH + NA * (5 + NC) + (size_t)a * NM) * NHW + p;
#pragma unroll 8
            for (int mi = 0; mi < NM; ++mi)
                out[o + 5 + mi] = __ldg(mb + mi * NHW);
        }
    }
}

extern "C" void kernel_launch(void* const* d_in, const int* in_sizes, int n_in,
                              void* d_out, int out_size)
{
    const float* in      = (const float*)d_in[0];
    const float* anchors = (const float*)d_in[1];
    float* out = (float*)d_out;

    fused_kernel<<<NBLK, TPB>>>(in, anchors, out, (long long)out_size);
}